// round 2
// baseline (speedup 1.0000x reference)
#include <cuda_runtime.h>
#include <math.h>

// ---------------------------------------------------------------------------
// QueryInstanceDecoder: fp32 baseline, fully fused-epilogue GEMM pipeline.
// N=262144, C_IN=72, D=256, Q=128.
// d_out layout (floats): mask_logits[128*N] | score[128] | point_embed[N*256] | refined[128*256]
// ---------------------------------------------------------------------------

#define DEVI __device__ __forceinline__

DEVI float geluf(float x) { return 0.5f * x * (1.0f + erff(x * 0.70710678118654752f)); }

// ---------------- scratch (static device memory; no allocations) -----------
#define NMAX 262144
__device__ float g_T1[(size_t)NMAX * 256];   // also reused as A2
__device__ float g_H[(size_t)NMAX * 256];
__device__ float g_meanN[NMAX];
__device__ float g_rstdN[NMAX];
__device__ float g_invpe[NMAX];
__device__ float g_meanQ[128];
__device__ float g_rstdQ[128];
__device__ float g_A2q[128 * 256];           // also reused for score-head hidden
__device__ float g_qe[128 * 256];
__device__ float g_qm[128 * 256];
__device__ float g_invq[128];
__device__ float g_spart[(NMAX / 128) * 128];        // [nblk][128]
__device__ float g_Ppart[256 * 128 * 256];           // [256 chunks][128][256]

// ---------------- generic 64x256 GEMM with fused transforms ----------------
// out[M x 256] = Aop(A[M x K]) @ B[K x 256], epilogue per flags.
// Block tile: 64 rows x 256 cols, 256 threads, 8x8 per-thread microtile.
// Split-K via blockIdx.y (Kblk columns of A / rows of B per y-block), out
// partials stacked at out + blockIdx.y * Mtot*256.

enum { AOP_ID = 0, AOP_LN = 1, AOP_LNGELU = 2, AOP_EXP = 3 };
#define EPI_BIAS  1
#define EPI_GELU  2
#define EPI_RESID 4
#define EPI_NORM  8

template <int AOP, int EPI>
__global__ __launch_bounds__(256)
void gemm256(const float* __restrict__ A, int lda,
             const float* __restrict__ B,
             const float* __restrict__ bias,
             float* __restrict__ out,
             int Kblk,
             const float* __restrict__ mean, const float* __restrict__ rstd,
             const float* __restrict__ lng,  const float* __restrict__ lnb,
             const float* __restrict__ resid,
             float* __restrict__ invn,
             int Mtot)
{
    __shared__ float As[16][64];
    __shared__ float Bs[16][256];

    const int tid  = threadIdx.x;
    const int row0 = blockIdx.x * 64;
    const long kbase = (long)blockIdx.y * Kblk;
    const float* Ab = A + kbase;          // column offset into A
    const float* Bb = B + kbase * 256;    // row offset into B
    float* outb = out + (size_t)blockIdx.y * (size_t)Mtot * 256;

    const int ar = tid >> 2, ac = (tid & 3) * 4;   // A-tile loader coords
    const int bkr = tid >> 4, bc = (tid & 15) * 16; // B-tile loader coords
    const int tr = tid >> 5, tc = tid & 31;        // compute coords

    float acc[8][8];
#pragma unroll
    for (int i = 0; i < 8; i++)
#pragma unroll
        for (int j = 0; j < 8; j++) acc[i][j] = 0.f;

    float m_r = 0.f, r_r = 0.f;
    if (AOP == AOP_LN || AOP == AOP_LNGELU) {
        m_r = mean[row0 + ar];
        r_r = rstd[row0 + ar];
    }

    for (int k0 = 0; k0 < Kblk; k0 += 16) {
        // ---- load A tile (64 x 16), transform, store transposed ----
        {
            const int kl = k0 + ac;
            float v[4];
            const float* ap = Ab + (size_t)(row0 + ar) * lda + kl;
            if (kl + 3 < Kblk) {
                float4 t = *(const float4*)ap;
                v[0] = t.x; v[1] = t.y; v[2] = t.z; v[3] = t.w;
            } else {
#pragma unroll
                for (int i = 0; i < 4; i++) v[i] = (kl + i < Kblk) ? ap[i] : 0.f;
            }
#pragma unroll
            for (int i = 0; i < 4; i++) {
                float x = v[i];
                if (AOP == AOP_LN || AOP == AOP_LNGELU) {
                    x = (x - m_r) * r_r * lng[kl + i] + lnb[kl + i];
                    if (AOP == AOP_LNGELU) x = geluf(x);
                } else if (AOP == AOP_EXP) {
                    x = expf(x);
                }
                As[ac + i][ar] = x;   // padded k entries get zeroed via Bs rows
            }
        }
        // ---- load B tile (16 x 256) ----
        {
            const int kb = k0 + bkr;
            const float* bp = Bb + (size_t)kb * 256 + bc;
            const bool ok = (kb < Kblk);
#pragma unroll
            for (int j = 0; j < 4; j++) {
                float4 t = ok ? *(const float4*)(bp + j * 4)
                              : make_float4(0.f, 0.f, 0.f, 0.f);
                *(float4*)&Bs[bkr][bc + j * 4] = t;
            }
        }
        __syncthreads();

#pragma unroll
        for (int kt = 0; kt < 16; kt++) {
            float4 a0 = *(const float4*)&As[kt][tr * 8];
            float4 a1 = *(const float4*)&As[kt][tr * 8 + 4];
            float4 b0 = *(const float4*)&Bs[kt][tc * 8];
            float4 b1 = *(const float4*)&Bs[kt][tc * 8 + 4];
            float a[8] = {a0.x, a0.y, a0.z, a0.w, a1.x, a1.y, a1.z, a1.w};
            float b[8] = {b0.x, b0.y, b0.z, b0.w, b1.x, b1.y, b1.z, b1.w};
#pragma unroll
            for (int i = 0; i < 8; i++)
#pragma unroll
                for (int j = 0; j < 8; j++) acc[i][j] += a[i] * b[j];
        }
        __syncthreads();
    }

    // ---- epilogue ----
#pragma unroll
    for (int i = 0; i < 8; i++) {
        const int row = row0 + tr * 8 + i;
#pragma unroll
        for (int j = 0; j < 8; j++) {
            const int c = tc * 8 + j;
            float v = acc[i][j];
            if (EPI & EPI_BIAS)  v += bias[c];
            if (EPI & EPI_GELU)  v = geluf(v);
            if (EPI & EPI_RESID) v += resid[(size_t)row * 256 + c];
            acc[i][j] = v;
        }
        float* op = outb + (size_t)row * 256 + tc * 8;
        *(float4*)op       = make_float4(acc[i][0], acc[i][1], acc[i][2], acc[i][3]);
        *(float4*)(op + 4) = make_float4(acc[i][4], acc[i][5], acc[i][6], acc[i][7]);
        if (EPI & EPI_NORM) {
            float ss = 0.f;
#pragma unroll
            for (int j = 0; j < 8; j++) ss += acc[i][j] * acc[i][j];
#pragma unroll
            for (int o = 16; o; o >>= 1) ss += __shfl_xor_sync(0xffffffffu, ss, o);
            if (tc == 0) invn[row] = 1.0f / fmaxf(sqrtf(ss), 1e-12f);
        }
    }
}

// ---------------- LN row statistics: [M x 256] -> mean, rstd ---------------
__global__ __launch_bounds__(256)
void ln_stats(const float* __restrict__ X, float* __restrict__ mean,
              float* __restrict__ rstd, int M)
{
    int warp = (blockIdx.x * blockDim.x + threadIdx.x) >> 5;
    if (warp >= M) return;
    int lane = threadIdx.x & 31;
    const float* row = X + (size_t)warp * 256;
    float s = 0.f, ss = 0.f;
#pragma unroll
    for (int j = 0; j < 8; j++) {
        float v = row[lane + 32 * j];
        s += v; ss += v * v;
    }
#pragma unroll
    for (int o = 16; o; o >>= 1) {
        s  += __shfl_xor_sync(0xffffffffu, s, o);
        ss += __shfl_xor_sync(0xffffffffu, ss, o);
    }
    if (lane == 0) {
        float m = s * (1.0f / 256.0f);
        float var = ss * (1.0f / 256.0f) - m * m;
        mean[warp] = m;
        rstd[warp] = rsqrtf(var + 1e-5f);
    }
}

// -------- qm = qe * inv_norm(row) * exp(logit_scale), [128 x 256] ----------
__global__ void qm_kernel(const float* __restrict__ qe, const float* __restrict__ invq,
                          const float* __restrict__ lsc, float* __restrict__ qm)
{
    int idx = blockIdx.x * 256 + threadIdx.x;
    int r = idx >> 8;
    qm[idx] = qe[idx] * invq[r] * expf(lsc[0]);
}

// ------- mask logits: L[128 x N] = qm @ (pe * invpe)^T, + per-chunk exp-sums
__global__ __launch_bounds__(256)
void mask_kernel(const float* __restrict__ qm, const float* __restrict__ pe,
                 const float* __restrict__ invpe, float* __restrict__ out,
                 float* __restrict__ spart, int N)
{
    __shared__ float Qs[16][128];
    __shared__ float Ps[16][128];
    const int tid = threadIdx.x;
    const int n0 = blockIdx.x * 128;

    const int lr = tid >> 1, lc = (tid & 1) * 8; // loader coords (rows 0..127)
    const int tr2 = tid >> 4, tc2 = tid & 15;    // compute coords

    float acc[8][8];
#pragma unroll
    for (int i = 0; i < 8; i++)
#pragma unroll
        for (int j = 0; j < 8; j++) acc[i][j] = 0.f;

    const float sc = invpe[n0 + lr];

    for (int k0 = 0; k0 < 256; k0 += 16) {
        {
            const float* qp = qm + (size_t)lr * 256 + k0 + lc;
            float4 t0 = *(const float4*)qp;
            float4 t1 = *(const float4*)(qp + 4);
            Qs[lc + 0][lr] = t0.x; Qs[lc + 1][lr] = t0.y;
            Qs[lc + 2][lr] = t0.z; Qs[lc + 3][lr] = t0.w;
            Qs[lc + 4][lr] = t1.x; Qs[lc + 5][lr] = t1.y;
            Qs[lc + 6][lr] = t1.z; Qs[lc + 7][lr] = t1.w;
        }
        {
            const float* pp = pe + (size_t)(n0 + lr) * 256 + k0 + lc;
            float4 t0 = *(const float4*)pp;
            float4 t1 = *(const float4*)(pp + 4);
            Ps[lc + 0][lr] = t0.x * sc; Ps[lc + 1][lr] = t0.y * sc;
            Ps[lc + 2][lr] = t0.z * sc; Ps[lc + 3][lr] = t0.w * sc;
            Ps[lc + 4][lr] = t1.x * sc; Ps[lc + 5][lr] = t1.y * sc;
            Ps[lc + 6][lr] = t1.z * sc; Ps[lc + 7][lr] = t1.w * sc;
        }
        __syncthreads();
#pragma unroll
        for (int kt = 0; kt < 16; kt++) {
            float4 a0 = *(const float4*)&Qs[kt][tr2 * 8];
            float4 a1 = *(const float4*)&Qs[kt][tr2 * 8 + 4];
            float4 b0 = *(const float4*)&Ps[kt][tc2 * 8];
            float4 b1 = *(const float4*)&Ps[kt][tc2 * 8 + 4];
            float a[8] = {a0.x, a0.y, a0.z, a0.w, a1.x, a1.y, a1.z, a1.w};
            float b[8] = {b0.x, b0.y, b0.z, b0.w, b1.x, b1.y, b1.z, b1.w};
#pragma unroll
            for (int i = 0; i < 8; i++)
#pragma unroll
                for (int j = 0; j < 8; j++) acc[i][j] += a[i] * b[j];
        }
        __syncthreads();
    }

#pragma unroll
    for (int i = 0; i < 8; i++) {
        const int q = tr2 * 8 + i;
        float* op = out + (size_t)q * N + n0 + tc2 * 8;
        *(float4*)op       = make_float4(acc[i][0], acc[i][1], acc[i][2], acc[i][3]);
        *(float4*)(op + 4) = make_float4(acc[i][4], acc[i][5], acc[i][6], acc[i][7]);
        float s = 0.f;
#pragma unroll
        for (int j = 0; j < 8; j++) s += expf(acc[i][j]);
#pragma unroll
        for (int o = 8; o; o >>= 1) s += __shfl_xor_sync(0xffffffffu, s, o, 16);
        if (tc2 == 0) spart[(size_t)blockIdx.x * 128 + q] = s;
    }
}

// -------- refined = qe + (sum_c Ppart) / (sum_i spart) ----------------------
__global__ __launch_bounds__(256)
void reduce_refined(const float* __restrict__ Ppart, const float* __restrict__ spart,
                    const float* __restrict__ qe, float* __restrict__ refined,
                    int CH, int NB)
{
    const int q = blockIdx.x;
    const int d = threadIdx.x;
    __shared__ float sh[256];
    float s = 0.f;
    for (int i = d; i < NB; i += 256) s += spart[(size_t)i * 128 + q];
    sh[d] = s;
    __syncthreads();
    for (int o = 128; o; o >>= 1) {
        if (d < o) sh[d] += sh[d + o];
        __syncthreads();
    }
    const float stot = sh[0];
    float p = 0.f;
    for (int c = 0; c < CH; c++) p += Ppart[((size_t)c * 128 + q) * 256 + d];
    refined[(size_t)q * 256 + d] = qe[(size_t)q * 256 + d] + p / stot;
}

// -------- score = A2s @ sh_w2 + sh_b2 ---------------------------------------
__global__ __launch_bounds__(256)
void score_kernel(const float* __restrict__ A2s, const float* __restrict__ w2,
                  const float* __restrict__ b2, float* __restrict__ out)
{
    const int q = blockIdx.x;
    const int d = threadIdx.x;
    __shared__ float sh[256];
    sh[d] = A2s[(size_t)q * 256 + d] * w2[d];
    __syncthreads();
    for (int o = 128; o; o >>= 1) {
        if (d < o) sh[d] += sh[d + o];
        __syncthreads();
    }
    if (d == 0) out[q] = sh[0] + b2[0];
}

// ---------------------------------------------------------------------------
extern "C" void kernel_launch(void* const* d_in, const int* in_sizes, int n_in,
                              void* d_out, int out_size)
{
    const float* point_feat = (const float*)d_in[0];
    const float* ip_w1 = (const float*)d_in[1];
    const float* ip_b1 = (const float*)d_in[2];
    const float* ip_ln_g = (const float*)d_in[3];
    const float* ip_ln_b = (const float*)d_in[4];
    const float* ip_w2 = (const float*)d_in[5];
    const float* ip_b2 = (const float*)d_in[6];
    const float* ph_ln_g = (const float*)d_in[7];
    const float* ph_ln_b = (const float*)d_in[8];
    const float* ph_w1 = (const float*)d_in[9];
    const float* ph_b1 = (const float*)d_in[10];
    const float* ph_w2 = (const float*)d_in[11];
    const float* ph_b2 = (const float*)d_in[12];
    const float* q_embed = (const float*)d_in[13];
    const float* qh_ln_g = (const float*)d_in[14];
    const float* qh_ln_b = (const float*)d_in[15];
    const float* qh_w1 = (const float*)d_in[16];
    const float* qh_b1 = (const float*)d_in[17];
    const float* qh_w2 = (const float*)d_in[18];
    const float* qh_b2 = (const float*)d_in[19];
    const float* sh_ln_g = (const float*)d_in[20];
    const float* sh_ln_b = (const float*)d_in[21];
    const float* sh_w1 = (const float*)d_in[22];
    const float* sh_b1 = (const float*)d_in[23];
    const float* sh_w2 = (const float*)d_in[24];
    const float* sh_b2 = (const float*)d_in[25];
    const float* logit_scale = (const float*)d_in[26];

    const int N = in_sizes[0] / 72;

    float* out = (float*)d_out;
    const size_t offScore = (size_t)128 * N;
    const size_t offPE = offScore + 128;
    const size_t offRef = offPE + (size_t)N * 256;
    float* mask = out;
    float* score = out + offScore;
    float* pe = out + offPE;
    float* refined = out + offRef;

    float *T1, *H, *meanN, *rstdN, *invpe, *meanQ, *rstdQ, *A2q, *qe, *qm, *invq,
          *spart, *Ppart;
    cudaGetSymbolAddress((void**)&T1, g_T1);
    cudaGetSymbolAddress((void**)&H, g_H);
    cudaGetSymbolAddress((void**)&meanN, g_meanN);
    cudaGetSymbolAddress((void**)&rstdN, g_rstdN);
    cudaGetSymbolAddress((void**)&invpe, g_invpe);
    cudaGetSymbolAddress((void**)&meanQ, g_meanQ);
    cudaGetSymbolAddress((void**)&rstdQ, g_rstdQ);
    cudaGetSymbolAddress((void**)&A2q, g_A2q);
    cudaGetSymbolAddress((void**)&qe, g_qe);
    cudaGetSymbolAddress((void**)&qm, g_qm);
    cudaGetSymbolAddress((void**)&invq, g_invq);
    cudaGetSymbolAddress((void**)&spart, g_spart);
    cudaGetSymbolAddress((void**)&Ppart, g_Ppart);

    // -------- point pipeline --------
    // T1 = point_feat @ ip_w1 + ip_b1
    gemm256<AOP_ID, EPI_BIAS><<<N / 64, 256>>>(
        point_feat, 72, ip_w1, ip_b1, T1, 72,
        nullptr, nullptr, nullptr, nullptr, nullptr, nullptr, N);
    ln_stats<<<N / 8, 256>>>(T1, meanN, rstdN, N);
    // H = gelu(LN(T1)) @ ip_w2 + ip_b2
    gemm256<AOP_LNGELU, EPI_BIAS><<<N / 64, 256>>>(
        T1, 256, ip_w2, ip_b2, H, 256,
        meanN, rstdN, ip_ln_g, ip_ln_b, nullptr, nullptr, N);
    ln_stats<<<N / 8, 256>>>(H, meanN, rstdN, N);
    // A2 (reuses T1) = gelu(LN(H) @ ph_w1 + ph_b1)
    gemm256<AOP_LN, EPI_BIAS | EPI_GELU><<<N / 64, 256>>>(
        H, 256, ph_w1, ph_b1, T1, 256,
        meanN, rstdN, ph_ln_g, ph_ln_b, nullptr, nullptr, N);
    // pe = H + A2 @ ph_w2 + ph_b2 ; invpe = 1/max(||pe||,1e-12)
    gemm256<AOP_ID, EPI_BIAS | EPI_RESID | EPI_NORM><<<N / 64, 256>>>(
        T1, 256, ph_w2, ph_b2, pe, 256,
        nullptr, nullptr, nullptr, nullptr, H, invpe, N);

    // -------- query pipeline --------
    ln_stats<<<16, 256>>>(q_embed, meanQ, rstdQ, 128);
    gemm256<AOP_LN, EPI_BIAS | EPI_GELU><<<2, 256>>>(
        q_embed, 256, qh_w1, qh_b1, A2q, 256,
        meanQ, rstdQ, qh_ln_g, qh_ln_b, nullptr, nullptr, 128);
    gemm256<AOP_ID, EPI_BIAS | EPI_RESID | EPI_NORM><<<2, 256>>>(
        A2q, 256, qh_w2, qh_b2, qe, 256,
        nullptr, nullptr, nullptr, nullptr, q_embed, invq, 128);
    qm_kernel<<<128, 256>>>(qe, invq, logit_scale, qm);

    // -------- mask logits + softmax partial sums --------
    mask_kernel<<<N / 128, 256>>>(qm, pe, invpe, mask, spart, N);

    // -------- weighted aggregation: Ppart[c] = exp(L_chunk) @ pe_chunk -------
    {
        dim3 grid(2, 256);  // 2 M-blocks of 64 rows, 256 K-chunks of 1024
        gemm256<AOP_EXP, 0><<<grid, 256>>>(
            mask, N, pe, nullptr, Ppart, 1024,
            nullptr, nullptr, nullptr, nullptr, nullptr, nullptr, 128);
    }
    reduce_refined<<<128, 256>>>(Ppart, spart, qe, refined, 256, N / 128);

    // -------- score head --------
    ln_stats<<<16, 256>>>(refined, meanQ, rstdQ, 128);
    gemm256<AOP_LN, EPI_BIAS | EPI_GELU><<<2, 256>>>(
        refined, 256, sh_w1, sh_b1, A2q, 256,
        meanQ, rstdQ, sh_ln_g, sh_ln_b, nullptr, nullptr, 128);
    score_kernel<<<128, 256>>>(A2q, sh_w2, sh_b2, score);
}